// round 9
// baseline (speedup 1.0000x reference)
#include <cuda_runtime.h>
#include <math.h>

#define B_    4
#define NH    4
#define HD    64
#define DEPTH 256
#define CG    17
#define PQ    4096   // 64*64
#define PK    1024   // 32*32
#define SCALE 0.125f // 64^-0.5

typedef unsigned long long u64;

// ---------------- packed fp32x2 helpers (Blackwell FFMA2 path) ----------------
__device__ __forceinline__ u64 fma2(u64 a, u64 b, u64 c) {
    u64 d; asm("fma.rn.f32x2 %0, %1, %2, %3;" : "=l"(d) : "l"(a), "l"(b), "l"(c)); return d;
}
__device__ __forceinline__ u64 add2(u64 a, u64 b) {
    u64 d; asm("add.rn.f32x2 %0, %1, %2;" : "=l"(d) : "l"(a), "l"(b)); return d;
}
__device__ __forceinline__ u64 mul2(u64 a, u64 b) {
    u64 d; asm("mul.rn.f32x2 %0, %1, %2;" : "=l"(d) : "l"(a), "l"(b)); return d;
}
__device__ __forceinline__ u64 pack2(float x, float y) {
    u64 d; asm("mov.b64 %0, {%1, %2};" : "=l"(d) : "f"(x), "f"(y)); return d;
}
__device__ __forceinline__ u64 bcast2(float x) { return pack2(x, x); }
__device__ __forceinline__ float2 unpk2(u64 v) {
    float2 r; asm("mov.b64 {%0, %1}, %2;" : "=f"(r.x), "=f"(r.y) : "l"(v)); return r;
}

// ---------------- scratch (device globals; no allocations allowed) ----------------
__device__ float g_q [B_*DEPTH*PQ];   // [b][nh*64+d][p]
__device__ float g_k [B_*DEPTH*PK];
__device__ float g_v [B_*DEPTH*PK];
__device__ float g_qc[B_*NH*CG*PQ];   // [b][nh][g][p]
__device__ float g_kc[B_*NH*CG*PK];

// ---------------- zero-fill (both conv outputs in one launch) ----------------
__global__ void zero_kernel(float* __restrict__ p0, int n0, float* __restrict__ p1, int n1) {
    int i = blockIdx.x * blockDim.x + threadIdx.x;
    if (i < n0) p0[i] = 0.f;
    else if (i < n0 + n1) p1[i - n0] = 0.f;
}

// ---------------- merged 1x1 projections: one launch for Q, K, V ----------------
__global__ void __launch_bounds__(256) proj_all_kernel(
    const float* __restrict__ wq, const float* __restrict__ xq, float* __restrict__ qo,
    const float* __restrict__ wk, const float* __restrict__ wv,
    const float* __restrict__ xkv, float* __restrict__ ko, float* __restrict__ vo)
{
    __shared__ float Ws[64 * 16];    // [m][kk]
    __shared__ float Xs[16 * 128];   // [kk][n]
    int t  = threadIdx.x;
    int tx = t & 15;     // n-group: n = tx*8 + j
    int ty = t >> 4;     // m-group: m = ty*4 + i

    int id = blockIdx.x;
    const float* Wp; const float* Xb; float* Cb; int P, n0, m0, bz;
    if (id < 512) {
        P = PQ; Wp = wq;
        n0 = (id & 31) * 128; m0 = ((id >> 5) & 3) * 64; bz = id >> 7;
        Xb = xq; Cb = qo;
    } else {
        int r = id - 512; int sel = r >> 7; r &= 127;
        P = PK;
        n0 = (r & 7) * 128; m0 = ((r >> 3) & 3) * 64; bz = r >> 5;
        Xb = xkv;
        Wp = sel ? wv : wk;
        Cb = sel ? vo : ko;
    }
    Xb += (size_t)bz * DEPTH * P;
    Cb += (size_t)bz * DEPTH * P;

    u64 acc[4][4];
#pragma unroll
    for (int i = 0; i < 4; ++i)
#pragma unroll
        for (int jh = 0; jh < 4; ++jh) acc[i][jh] = 0ull;

    for (int k0 = 0; k0 < DEPTH; k0 += 16) {
#pragma unroll
        for (int it = 0; it < 4; ++it) {
            int i = t + it * 256;
            int m = i >> 4, kk = i & 15;
            Ws[m * 16 + kk] = Wp[(size_t)(m0 + m) * DEPTH + k0 + kk];
        }
#pragma unroll
        for (int it = 0; it < 8; ++it) {
            int i = t + it * 256;
            int n = i & 127, kk = i >> 7;
            Xs[kk * 128 + n] = Xb[(size_t)(k0 + kk) * P + n0 + n];
        }
        __syncthreads();
#pragma unroll
        for (int kk = 0; kk < 16; ++kk) {
            u64 ap[4];
#pragma unroll
            for (int i = 0; i < 4; ++i) ap[i] = bcast2(Ws[(ty * 4 + i) * 16 + kk]);
            ulonglong2 b01 = *(const ulonglong2*)&Xs[kk * 128 + tx * 8];
            ulonglong2 b23 = *(const ulonglong2*)&Xs[kk * 128 + tx * 8 + 4];
            u64 bp[4] = {b01.x, b01.y, b23.x, b23.y};
#pragma unroll
            for (int i = 0; i < 4; ++i)
#pragma unroll
                for (int jh = 0; jh < 4; ++jh) acc[i][jh] = fma2(ap[i], bp[jh], acc[i][jh]);
        }
        __syncthreads();
    }
#pragma unroll
    for (int i = 0; i < 4; ++i) {
        float* cp = Cb + (size_t)(m0 + ty * 4 + i) * P + n0 + tx * 8;
        *(ulonglong2*)(cp)     = make_ulonglong2(acc[i][0], acc[i][1]);
        *(ulonglong2*)(cp + 4) = make_ulonglong2(acc[i][2], acc[i][3]);
    }
}

// ---------------- merged compress conv3d (q side + k side in one launch) ----------------
// xs stored as DUPLICATED u64 pairs -> inner-loop x operand is one LDS.64, no MOV.
// Dynamic smem (64.3 KB > 48 KB static limit): xs 6080 u64, then es 3920 floats.
#define CONV_SMEM_BYTES (4*38*40*8 + 4*49*20*4)
__global__ void __launch_bounds__(256) compress_all_kernel(
    const float* __restrict__ xqs, const float* __restrict__ embq, float* __restrict__ outq,
    const float* __restrict__ xks, const float* __restrict__ embk, float* __restrict__ outk)
{
    extern __shared__ u64 smc[];
    u64*   xs = smc;                       // [4][38][40] dup pairs, 48.6 KB
    float* es = (float*)(smc + 4*38*40);   // [4][49][20], 15.7 KB

    int t  = threadIdx.x;
    int tx = t & 31, ty = t >> 5;

    int id = blockIdx.x;
    const float* xin; const float* emb; float* out;
    int IMG, NCHv, c0, bnh, X0, Y0;
    if (id < 512) {
        IMG = 64; NCHv = 8;
        int tile = id & 3;
        bnh = (id >> 2) & 15;
        c0  = (id >> 6) * 8;
        X0 = (tile & 1) * 32; Y0 = (tile >> 1) * 32;
        xin = xqs; emb = embq; out = outq;
    } else {
        int r = id - 512;
        IMG = 32; NCHv = 4;
        bnh = r & 15;
        c0  = (r >> 4) * 4;
        X0 = 0; Y0 = 0;
        xin = xks; emb = embk; out = outk;
    }
    int b = bnh >> 2, nh = bnh & 3;
    int imgsq = IMG * IMG;

    u64 acc[4][9];
#pragma unroll
    for (int r = 0; r < 4; ++r)
#pragma unroll
        for (int pg = 0; pg < 9; ++pg) acc[r][pg] = 0ull;

    for (int dn = -1; dn <= 1; ++dn) {
        int ns = nh + dn;
        if (ns < 0 || ns >= NH) continue;
        const float* xp = xin + (size_t)(b * NH + ns) * HD * imgsq;
        for (int dc = c0; dc < c0 + NCHv; dc += 4) {
            for (int i = t; i < 4 * 49 * 20; i += 256) {
                int g = i % 20; int r = i / 20;
                int tap = r % 49; int dd = r / 49;
                es[(dd * 49 + tap) * 20 + g] = (g < 17)
                    ? emb[((size_t)(g * HD + dc + dd) * 3 + (dn + 1)) * 49 + tap] : 0.f;
            }
            for (int i = t; i < 4 * 38 * 38; i += 256) {
                int cx = i % 38; int r = i / 38;
                int ry = r % 38; int dd = r / 38;
                int gy = Y0 + ry - 3, gx = X0 + cx - 3;
                float v = 0.f;
                if (gy >= 0 && gy < IMG && gx >= 0 && gx < IMG)
                    v = xp[(size_t)(dc + dd) * imgsq + gy * IMG + gx];
                xs[(dd * 38 + ry) * 40 + cx] = bcast2(v);
            }
            __syncthreads();
#pragma unroll
            for (int dd = 0; dd < 4; ++dd) {
                for (int ky = 0; ky < 7; ++ky) {
                    const u64* xr0 = &xs[(dd * 38 + ty      + ky) * 40 + tx];
                    const u64* xr1 = &xs[(dd * 38 + ty +  8 + ky) * 40 + tx];
                    const u64* xr2 = &xs[(dd * 38 + ty + 16 + ky) * 40 + tx];
                    const u64* xr3 = &xs[(dd * 38 + ty + 24 + ky) * 40 + tx];
#pragma unroll
                    for (int kx = 0; kx < 7; ++kx) {
                        const u64* ep = (const u64*)&es[(dd * 49 + ky * 7 + kx) * 20];
                        ulonglong2 E0 = ((const ulonglong2*)ep)[0];
                        ulonglong2 E1 = ((const ulonglong2*)ep)[1];
                        ulonglong2 E2 = ((const ulonglong2*)ep)[2];
                        ulonglong2 E3 = ((const ulonglong2*)ep)[3];
                        u64 e8 = ep[8];
                        u64 e[9] = {E0.x, E0.y, E1.x, E1.y, E2.x, E2.y, E3.x, E3.y, e8};
                        u64 xp0 = xr0[kx];
                        u64 xp1 = xr1[kx];
                        u64 xp2 = xr2[kx];
                        u64 xp3 = xr3[kx];
#pragma unroll
                        for (int pg = 0; pg < 9; ++pg) {
                            acc[0][pg] = fma2(e[pg], xp0, acc[0][pg]);
                            acc[1][pg] = fma2(e[pg], xp1, acc[1][pg]);
                            acc[2][pg] = fma2(e[pg], xp2, acc[2][pg]);
                            acc[3][pg] = fma2(e[pg], xp3, acc[3][pg]);
                        }
                    }
                }
            }
            __syncthreads();
        }
    }

    size_t obase = (size_t)bnh * CG * imgsq;
#pragma unroll
    for (int r = 0; r < 4; ++r) {
        int p = (Y0 + ty + 8 * r) * IMG + X0 + tx;
#pragma unroll
        for (int pg = 0; pg < 9; ++pg) {
            float2 v = unpk2(acc[r][pg]);
            int g0 = 2 * pg;
            atomicAdd(&out[obase + (size_t)g0 * imgsq + p], v.x);
            if (g0 + 1 < CG)
                atomicAdd(&out[obase + (size_t)(g0 + 1) * imgsq + p], v.y);
        }
    }
}

// ---------------- attention ----------------
// per (b,nh): sim = softmax_k( scale * qc^T kc ), out[dd][q] = sum_k sim[q][k] v[dd][k] / l[q]
// kc and v staged as DUPLICATED u64 pairs (no bcast MOVs in the hot loops).
// v rows remapped r=(d%8)*8+d/8 so the 8 per-warp phase-2 addresses hit distinct bank-pairs.
// smem floats: qc 2176 + kc2 2176 + v2 8320 + l 256 + P 8192 = 21120 (84.5 KB)
#define ATTN_SMEM_FLOATS (17*128 + 2*(17*64) + 2*(64*65) + 2*128 + 64*128)
__global__ void __launch_bounds__(256, 2) attn_kernel(float* __restrict__ out)
{
    extern __shared__ float sm[];
    float* qc_s = sm;                        // [g][128]
    u64*   kc2  = (u64*)(qc_s + 17 * 128);   // [g][64] dup pairs
    u64*   v2   = kc2 + 17 * 64;             // [r][65] dup pairs, r=(d%8)*8+d/8
    float* l_s  = (float*)(v2 + 64 * 65);    // [2][128]
    float* P_s  = l_s + 2 * 128;             // [k][128]; reused as mrg[d][128] in epilogue

    int t  = threadIdx.x;
    // phase-1 mapping
    int tq1 = t & 15;        // q = tq1*8 + j
    int td1 = t >> 4;        // k = td1*4 + i
    // phase-2 mapping
    int kh  = t >> 7;        // k-half (0/1)
    int r2  = t & 127;
    int tq2 = r2 >> 3;       // q = tq2*8 + j
    int td2 = r2 & 7;        // d = td2*8 + jd

    int q0  = blockIdx.x * 128;
    int bnh = blockIdx.y;
    int b = bnh >> 2, nh = bnh & 3;

    const float* qc = g_qc + (size_t)bnh * CG * PQ;
    const float* kc = g_kc + (size_t)bnh * CG * PK;
    const float* v  = g_v  + ((size_t)b * DEPTH + nh * HD) * PK;

    for (int i = t; i < CG * 128; i += 256) {
        int g = i >> 7, q = i & 127;
        qc_s[g * 128 + q] = qc[(size_t)g * PQ + q0 + q];
    }

    u64 acc[4][8];   // [jh q-pair][jd d]
#pragma unroll
    for (int jh = 0; jh < 4; ++jh)
#pragma unroll
        for (int jd = 0; jd < 8; ++jd) acc[jh][jd] = 0ull;
    u64 lacc[4] = {0ull, 0ull, 0ull, 0ull};   // used by td2==0 threads
    __syncthreads();

    for (int kk0 = 0; kk0 < PK; kk0 += 64) {
        for (int i = t; i < CG * 64; i += 256) {
            int g = i >> 6, k = i & 63;
            kc2[g * 64 + k] = bcast2(kc[(size_t)g * PK + kk0 + k]);
        }
#pragma unroll
        for (int it = 0; it < 16; ++it) {
            int i = t + it * 256;
            int k = i & 63, dd = i >> 6;
            int r = (dd & 7) * 8 + (dd >> 3);
            v2[r * 65 + k] = bcast2(v[(size_t)dd * PK + kk0 + k]);
        }
        __syncthreads();

        // phase 1: s[4k][8q] -> exp -> P_s
        {
            u64 sp[4][4];
#pragma unroll
            for (int i = 0; i < 4; ++i)
#pragma unroll
                for (int jh = 0; jh < 4; ++jh) sp[i][jh] = 0ull;
#pragma unroll
            for (int g = 0; g < CG; ++g) {
                const ulonglong2* kr = (const ulonglong2*)&kc2[g * 64 + td1 * 4];
                ulonglong2 k01 = kr[0];
                ulonglong2 k23 = kr[1];
                u64 kp[4] = {k01.x, k01.y, k23.x, k23.y};
                ulonglong2 qa = *(const ulonglong2*)&qc_s[g * 128 + tq1 * 8];
                ulonglong2 qb = *(const ulonglong2*)&qc_s[g * 128 + tq1 * 8 + 4];
                u64 qp[4] = {qa.x, qa.y, qb.x, qb.y};
#pragma unroll
                for (int i = 0; i < 4; ++i)
#pragma unroll
                    for (int jh = 0; jh < 4; ++jh) sp[i][jh] = fma2(kp[i], qp[jh], sp[i][jh]);
            }
#pragma unroll
            for (int i = 0; i < 4; ++i) {
                int k = td1 * 4 + i;
                float p[8];
#pragma unroll
                for (int jh = 0; jh < 4; ++jh) {
                    float2 sv = unpk2(sp[i][jh]);
                    float z0 = fminf(fmaxf(sv.x * SCALE, -30.f), 30.f);
                    float z1 = fminf(fmaxf(sv.y * SCALE, -30.f), 30.f);
                    p[2 * jh]     = __expf(z0);
                    p[2 * jh + 1] = __expf(z1);
                }
                *(float4*)&P_s[k * 128 + tq1 * 8]     = make_float4(p[0], p[1], p[2], p[3]);
                *(float4*)&P_s[k * 128 + tq1 * 8 + 4] = make_float4(p[4], p[5], p[6], p[7]);
            }
        }
        __syncthreads();

        // phase 2: acc[q][d] += P[k][q] * v[d][k], each half covers 32 k
#pragma unroll 4
        for (int kk = 0; kk < 32; ++kk) {
            int k = kh * 32 + kk;
            ulonglong2 pa = *(const ulonglong2*)&P_s[k * 128 + tq2 * 8];
            ulonglong2 pb = *(const ulonglong2*)&P_s[k * 128 + tq2 * 8 + 4];
            u64 ap[4] = {pa.x, pa.y, pb.x, pb.y};
            if (td2 == 0) {
#pragma unroll
                for (int jh = 0; jh < 4; ++jh) lacc[jh] = add2(lacc[jh], ap[jh]);
            }
            u64 bp[8];
#pragma unroll
            for (int jd = 0; jd < 8; ++jd) bp[jd] = v2[(jd * 8 + td2) * 65 + k];
#pragma unroll
            for (int jh = 0; jh < 4; ++jh)
#pragma unroll
                for (int jd = 0; jd < 8; ++jd) acc[jh][jd] = fma2(ap[jh], bp[jd], acc[jh][jd]);
        }
        __syncthreads();
    }

    // epilogue: merge the two k-halves, apply 1/l, write out.
    if (td2 == 0) {
#pragma unroll
        for (int jh = 0; jh < 4; ++jh)
            ((u64*)l_s)[kh * 64 + tq2 * 4 + jh] = lacc[jh];
    }
    float* mrg = P_s;   // [d][128]
    if (kh == 0) {
#pragma unroll
        for (int jd = 0; jd < 8; ++jd) {
            int d = td2 * 8 + jd;
#pragma unroll
            for (int jh = 0; jh < 4; ++jh)
                *(u64*)&mrg[d * 128 + tq2 * 8 + 2 * jh] = acc[jh][jd];
        }
    }
    __syncthreads();
    if (kh == 1) {
        u64 linv[4];
#pragma unroll
        for (int jh = 0; jh < 4; ++jh) {
            u64 lsum = add2(((u64*)l_s)[tq2 * 4 + jh], ((u64*)l_s)[64 + tq2 * 4 + jh]);
            float2 lv = unpk2(lsum);
            linv[jh] = pack2(1.f / lv.x, 1.f / lv.y);
        }
#pragma unroll
        for (int jd = 0; jd < 8; ++jd) {
            int d = td2 * 8 + jd;
            u64 s[4];
#pragma unroll
            for (int jh = 0; jh < 4; ++jh) {
                u64 m = *(const u64*)&mrg[d * 128 + tq2 * 8 + 2 * jh];
                s[jh] = mul2(add2(m, acc[jh][jd]), linv[jh]);
            }
            float* op = out + ((size_t)b * DEPTH + nh * HD + d) * PQ + q0 + tq2 * 8;
            *(ulonglong2*)(op)     = make_ulonglong2(s[0], s[1]);
            *(ulonglong2*)(op + 4) = make_ulonglong2(s[2], s[3]);
        }
    }
}

// ---------------- launch ----------------
extern "C" void kernel_launch(void* const* d_in, const int* in_sizes, int n_in,
                              void* d_out, int out_size)
{
    (void)in_sizes; (void)n_in; (void)out_size;
    const float* xq    = (const float*)d_in[0];
    const float* xkv   = (const float*)d_in[1];
    const float* wq    = (const float*)d_in[2];
    const float* wk    = (const float*)d_in[3];
    const float* wv    = (const float*)d_in[4];
    const float* emb_q = (const float*)d_in[5];
    const float* emb_k = (const float*)d_in[6];
    float* out = (float*)d_out;

    float *q_p, *k_p, *v_p, *qc_p, *kc_p;
    cudaGetSymbolAddress((void**)&q_p,  g_q);
    cudaGetSymbolAddress((void**)&k_p,  g_k);
    cudaGetSymbolAddress((void**)&v_p,  g_v);
    cudaGetSymbolAddress((void**)&qc_p, g_qc);
    cudaGetSymbolAddress((void**)&kc_p, g_kc);

    const int NQC = B_ * NH * CG * PQ;
    const int NKC = B_ * NH * CG * PK;

    // launch 0: zero both conv outputs
    zero_kernel<<<(NQC + NKC + 1023) / 1024, 1024>>>(qc_p, NQC, kc_p, NKC);

    // launch 1: all three projections (768 blocks)
    proj_all_kernel<<<768, 256>>>(wq, xq, q_p, wk, wv, xkv, k_p, v_p);

    // launch 2: both conv sides (768 blocks), dynamic smem 64.3 KB
    cudaFuncSetAttribute(compress_all_kernel, cudaFuncAttributeMaxDynamicSharedMemorySize,
                         CONV_SMEM_BYTES);
    compress_all_kernel<<<768, 256, CONV_SMEM_BYTES>>>(q_p, emb_q, qc_p, k_p, emb_k, kc_p);

    // launch 3: attention
    cudaFuncSetAttribute(attn_kernel, cudaFuncAttributeMaxDynamicSharedMemorySize,
                         ATTN_SMEM_FLOATS * sizeof(float));
    attn_kernel<<<dim3(PQ / 128, B_ * NH), 256, ATTN_SMEM_FLOATS * sizeof(float)>>>(out);
}

// round 10
// speedup vs baseline: 1.0828x; 1.0828x over previous
#include <cuda_runtime.h>
#include <math.h>

#define B_    4
#define NH    4
#define HD    64
#define DEPTH 256
#define CG    17
#define PQ    4096   // 64*64
#define PK    1024   // 32*32
#define SCALE 0.125f // 64^-0.5

typedef unsigned long long u64;

// ---------------- packed fp32x2 helpers (Blackwell FFMA2 path) ----------------
__device__ __forceinline__ u64 fma2(u64 a, u64 b, u64 c) {
    u64 d; asm("fma.rn.f32x2 %0, %1, %2, %3;" : "=l"(d) : "l"(a), "l"(b), "l"(c)); return d;
}
__device__ __forceinline__ u64 add2(u64 a, u64 b) {
    u64 d; asm("add.rn.f32x2 %0, %1, %2;" : "=l"(d) : "l"(a), "l"(b)); return d;
}
__device__ __forceinline__ u64 mul2(u64 a, u64 b) {
    u64 d; asm("mul.rn.f32x2 %0, %1, %2;" : "=l"(d) : "l"(a), "l"(b)); return d;
}
__device__ __forceinline__ u64 pack2(float x, float y) {
    u64 d; asm("mov.b64 %0, {%1, %2};" : "=l"(d) : "f"(x), "f"(y)); return d;
}
__device__ __forceinline__ u64 bcast2(float x) { return pack2(x, x); }
__device__ __forceinline__ float2 unpk2(u64 v) {
    float2 r; asm("mov.b64 {%0, %1}, %2;" : "=f"(r.x), "=f"(r.y) : "l"(v)); return r;
}

// ---------------- scratch (device globals; no allocations allowed) ----------------
__device__ float g_q [B_*DEPTH*PQ];   // [b][nh*64+d][p]
__device__ float g_k [B_*DEPTH*PK];
__device__ float g_v [B_*DEPTH*PK];
__device__ float g_qc[B_*NH*CG*PQ];   // [b][nh][g][p]
__device__ float g_kc[B_*NH*CG*PK];

// ---------------- zero-fill (both conv outputs in one launch) ----------------
__global__ void zero_kernel(float* __restrict__ p0, int n0, float* __restrict__ p1, int n1) {
    int i = blockIdx.x * blockDim.x + threadIdx.x;
    if (i < n0) p0[i] = 0.f;
    else if (i < n0 + n1) p1[i - n0] = 0.f;
}

// ---------------- merged 1x1 projections: one launch for Q, K, V ----------------
__global__ void __launch_bounds__(256) proj_all_kernel(
    const float* __restrict__ wq, const float* __restrict__ xq, float* __restrict__ qo,
    const float* __restrict__ wk, const float* __restrict__ wv,
    const float* __restrict__ xkv, float* __restrict__ ko, float* __restrict__ vo)
{
    __shared__ float Ws[64 * 16];    // [m][kk]
    __shared__ float Xs[16 * 128];   // [kk][n]
    int t  = threadIdx.x;
    int tx = t & 15;     // n-group: n = tx*8 + j
    int ty = t >> 4;     // m-group: m = ty*4 + i

    int id = blockIdx.x;
    const float* Wp; const float* Xb; float* Cb; int P, n0, m0, bz;
    if (id < 512) {
        P = PQ; Wp = wq;
        n0 = (id & 31) * 128; m0 = ((id >> 5) & 3) * 64; bz = id >> 7;
        Xb = xq; Cb = qo;
    } else {
        int r = id - 512; int sel = r >> 7; r &= 127;
        P = PK;
        n0 = (r & 7) * 128; m0 = ((r >> 3) & 3) * 64; bz = r >> 5;
        Xb = xkv;
        Wp = sel ? wv : wk;
        Cb = sel ? vo : ko;
    }
    Xb += (size_t)bz * DEPTH * P;
    Cb += (size_t)bz * DEPTH * P;

    u64 acc[4][4];
#pragma unroll
    for (int i = 0; i < 4; ++i)
#pragma unroll
        for (int jh = 0; jh < 4; ++jh) acc[i][jh] = 0ull;

    for (int k0 = 0; k0 < DEPTH; k0 += 16) {
#pragma unroll
        for (int it = 0; it < 4; ++it) {
            int i = t + it * 256;
            int m = i >> 4, kk = i & 15;
            Ws[m * 16 + kk] = Wp[(size_t)(m0 + m) * DEPTH + k0 + kk];
        }
#pragma unroll
        for (int it = 0; it < 8; ++it) {
            int i = t + it * 256;
            int n = i & 127, kk = i >> 7;
            Xs[kk * 128 + n] = Xb[(size_t)(k0 + kk) * P + n0 + n];
        }
        __syncthreads();
#pragma unroll
        for (int kk = 0; kk < 16; ++kk) {
            u64 ap[4];
#pragma unroll
            for (int i = 0; i < 4; ++i) ap[i] = bcast2(Ws[(ty * 4 + i) * 16 + kk]);
            ulonglong2 b01 = *(const ulonglong2*)&Xs[kk * 128 + tx * 8];
            ulonglong2 b23 = *(const ulonglong2*)&Xs[kk * 128 + tx * 8 + 4];
            u64 bp[4] = {b01.x, b01.y, b23.x, b23.y};
#pragma unroll
            for (int i = 0; i < 4; ++i)
#pragma unroll
                for (int jh = 0; jh < 4; ++jh) acc[i][jh] = fma2(ap[i], bp[jh], acc[i][jh]);
        }
        __syncthreads();
    }
#pragma unroll
    for (int i = 0; i < 4; ++i) {
        float* cp = Cb + (size_t)(m0 + ty * 4 + i) * P + n0 + tx * 8;
        *(ulonglong2*)(cp)     = make_ulonglong2(acc[i][0], acc[i][1]);
        *(ulonglong2*)(cp + 4) = make_ulonglong2(acc[i][2], acc[i][3]);
    }
}

// ---------------- merged compress conv3d (q side + k side in one launch) ----------------
// R6 math (32x32 px tile, 4 px/thread, pairs over g), re-split for wave balance:
// [0,1024)   -> q side (IMG=64, NCH=4: 4 tiles x 16 bnh x 16 channel-splits)
// [1024,1280)-> k side (IMG=32, NCH=4: 16 bnh x 16 channel-splits)
// 1280 uniform blocks (each: 1 chunk per valid depth plane). atomicAdd epilogue.
__global__ void __launch_bounds__(256) compress_all_kernel(
    const float* __restrict__ xqs, const float* __restrict__ embq, float* __restrict__ outq,
    const float* __restrict__ xks, const float* __restrict__ embk, float* __restrict__ outk)
{
    __shared__ float xs[4][38][40];      // 24.3 KB
    __shared__ float es[4][49][20];      // 15.7 KB

    int t  = threadIdx.x;
    int tx = t & 31, ty = t >> 5;

    int id = blockIdx.x;
    const float* xin; const float* emb; float* out;
    int IMG, NCHv, c0, bnh, X0, Y0;
    if (id < 1024) {
        IMG = 64; NCHv = 4;
        int tile = id & 3;
        bnh = (id >> 2) & 15;
        c0  = (id >> 6) * 4;
        X0 = (tile & 1) * 32; Y0 = (tile >> 1) * 32;
        xin = xqs; emb = embq; out = outq;
    } else {
        int r = id - 1024;
        IMG = 32; NCHv = 4;
        bnh = r & 15;
        c0  = (r >> 4) * 4;
        X0 = 0; Y0 = 0;
        xin = xks; emb = embk; out = outk;
    }
    int b = bnh >> 2, nh = bnh & 3;
    int imgsq = IMG * IMG;

    u64 acc[4][9];
#pragma unroll
    for (int r = 0; r < 4; ++r)
#pragma unroll
        for (int pg = 0; pg < 9; ++pg) acc[r][pg] = 0ull;

    for (int dn = -1; dn <= 1; ++dn) {
        int ns = nh + dn;
        if (ns < 0 || ns >= NH) continue;
        const float* xp = xin + (size_t)(b * NH + ns) * HD * imgsq;
        for (int dc = c0; dc < c0 + NCHv; dc += 4) {
            for (int i = t; i < 4 * 49 * 20; i += 256) {
                int g = i % 20; int r = i / 20;
                int tap = r % 49; int dd = r / 49;
                es[dd][tap][g] = (g < 17)
                    ? emb[((size_t)(g * HD + dc + dd) * 3 + (dn + 1)) * 49 + tap] : 0.f;
            }
            for (int i = t; i < 4 * 38 * 38; i += 256) {
                int cx = i % 38; int r = i / 38;
                int ry = r % 38; int dd = r / 38;
                int gy = Y0 + ry - 3, gx = X0 + cx - 3;
                float v = 0.f;
                if (gy >= 0 && gy < IMG && gx >= 0 && gx < IMG)
                    v = xp[(size_t)(dc + dd) * imgsq + gy * IMG + gx];
                xs[dd][ry][cx] = v;
            }
            __syncthreads();
#pragma unroll
            for (int dd = 0; dd < 4; ++dd) {
                for (int ky = 0; ky < 7; ++ky) {
                    const float* xr0 = &xs[dd][ty      + ky][tx];
                    const float* xr1 = &xs[dd][ty +  8 + ky][tx];
                    const float* xr2 = &xs[dd][ty + 16 + ky][tx];
                    const float* xr3 = &xs[dd][ty + 24 + ky][tx];
#pragma unroll
                    for (int kx = 0; kx < 7; ++kx) {
                        const u64* ep = (const u64*)&es[dd][ky * 7 + kx][0];
                        ulonglong2 E0 = ((const ulonglong2*)ep)[0];
                        ulonglong2 E1 = ((const ulonglong2*)ep)[1];
                        ulonglong2 E2 = ((const ulonglong2*)ep)[2];
                        ulonglong2 E3 = ((const ulonglong2*)ep)[3];
                        u64 e8 = ep[8];
                        u64 e[9] = {E0.x, E0.y, E1.x, E1.y, E2.x, E2.y, E3.x, E3.y, e8};
                        u64 xp0 = bcast2(xr0[kx]);
                        u64 xp1 = bcast2(xr1[kx]);
                        u64 xp2 = bcast2(xr2[kx]);
                        u64 xp3 = bcast2(xr3[kx]);
#pragma unroll
                        for (int pg = 0; pg < 9; ++pg) {
                            acc[0][pg] = fma2(e[pg], xp0, acc[0][pg]);
                            acc[1][pg] = fma2(e[pg], xp1, acc[1][pg]);
                            acc[2][pg] = fma2(e[pg], xp2, acc[2][pg]);
                            acc[3][pg] = fma2(e[pg], xp3, acc[3][pg]);
                        }
                    }
                }
            }
            __syncthreads();
        }
    }

    size_t obase = (size_t)bnh * CG * imgsq;
#pragma unroll
    for (int r = 0; r < 4; ++r) {
        int p = (Y0 + ty + 8 * r) * IMG + X0 + tx;
#pragma unroll
        for (int pg = 0; pg < 9; ++pg) {
            float2 v = unpk2(acc[r][pg]);
            int g0 = 2 * pg;
            atomicAdd(&out[obase + (size_t)g0 * imgsq + p], v.x);
            if (g0 + 1 < CG)
                atomicAdd(&out[obase + (size_t)(g0 + 1) * imgsq + p], v.y);
        }
    }
}

// ---------------- attention (exact R6 version, best measured: 417 us) ----------------
// per (b,nh): sim = softmax_k( scale * qc^T kc ), out[dd][q] = sum_k sim[q][k] v[dd][k] / l[q]
// Block: 128 q's, K-chunks of 64. Logits clamped to [-30,30]; no max pass needed.
#define ATTN_SMEM_FLOATS (17*128 + 17*64 + 64*65 + 2*128 + 64*128)
__global__ void __launch_bounds__(256, 2) attn_kernel(float* __restrict__ out)
{
    extern __shared__ float sm[];
    float* qc_s = sm;                    // [g][128]
    float* kc_s = qc_s + 17 * 128;       // [g][64]
    float* v_s  = kc_s + 17 * 64;        // [dd][65]
    float* l_s  = v_s + 64 * 65;         // [2][128]
    float* P_s  = l_s + 2 * 128;         // [k][128]; reused as mrg[d][128] in epilogue

    int t  = threadIdx.x;
    // phase-1 mapping
    int tq1 = t & 15;        // q = tq1*8 + j
    int td1 = t >> 4;        // k = td1*4 + i
    // phase-2 mapping
    int kh  = t >> 7;        // k-half (0/1)
    int r2  = t & 127;
    int tq2 = r2 >> 3;       // q = tq2*8 + j
    int td2 = r2 & 7;        // d = td2*8 + jd

    int q0  = blockIdx.x * 128;
    int bnh = blockIdx.y;
    int b = bnh >> 2, nh = bnh & 3;

    const float* qc = g_qc + (size_t)bnh * CG * PQ;
    const float* kc = g_kc + (size_t)bnh * CG * PK;
    const float* v  = g_v  + ((size_t)b * DEPTH + nh * HD) * PK;

    for (int i = t; i < CG * 128; i += 256) {
        int g = i >> 7, q = i & 127;
        qc_s[g * 128 + q] = qc[(size_t)g * PQ + q0 + q];
    }

    u64 acc[4][8];   // [jh q-pair][jd d]
#pragma unroll
    for (int jh = 0; jh < 4; ++jh)
#pragma unroll
        for (int jd = 0; jd < 8; ++jd) acc[jh][jd] = 0ull;
    u64 lacc[4] = {0ull, 0ull, 0ull, 0ull};   // used by td2==0 threads
    __syncthreads();

    for (int kk0 = 0; kk0 < PK; kk0 += 64) {
        for (int i = t; i < CG * 64; i += 256) {
            int g = i >> 6, k = i & 63;
            kc_s[g * 64 + k] = kc[(size_t)g * PK + kk0 + k];
        }
#pragma unroll
        for (int it = 0; it < 16; ++it) {
            int i = t + it * 256;
            int k = i & 63, dd = i >> 6;
            v_s[dd * 65 + k] = v[(size_t)dd * PK + kk0 + k];
        }
        __syncthreads();

        // phase 1: s[4k][8q] -> exp -> P_s
        {
            u64 sp[4][4];
#pragma unroll
            for (int i = 0; i < 4; ++i)
#pragma unroll
                for (int jh = 0; jh < 4; ++jh) sp[i][jh] = 0ull;
#pragma unroll
            for (int g = 0; g < CG; ++g) {
                float4 kv = *(const float4*)&kc_s[g * 64 + td1 * 4];
                u64 kp[4] = {bcast2(kv.x), bcast2(kv.y), bcast2(kv.z), bcast2(kv.w)};
                ulonglong2 qa = *(const ulonglong2*)&qc_s[g * 128 + tq1 * 8];
                ulonglong2 qb = *(const ulonglong2*)&qc_s[g * 128 + tq1 * 8 + 4];
                u64 qp[4] = {qa.x, qa.y, qb.x, qb.y};
#pragma unroll
                for (int i = 0; i < 4; ++i)
#pragma unroll
                    for (int jh = 0; jh < 4; ++jh) sp[i][jh] = fma2(kp[i], qp[jh], sp[i][jh]);
            }
#pragma unroll
            for (int i = 0; i < 4; ++i) {
                int k = td1 * 4 + i;
                float p[8];
#pragma unroll
                for (int jh = 0; jh < 4; ++jh) {
                    float2 sv = unpk2(sp[i][jh]);
                    float z0 = fminf(fmaxf(sv.x * SCALE, -30.f), 30.f);
                    float z1 = fminf(fmaxf(sv.y * SCALE, -30.f), 30.f);
                    p[2 * jh]     = __expf(z0);
                    p[2 * jh + 1] = __expf(z1);
                }
                *(float4*)&P_s[k * 128 + tq1 * 8]     = make_float4(p[0], p[1], p[2], p[3]);
                *(float4*)&P_s[k * 128 + tq1 * 8 + 4] = make_float4(p[4], p[5], p[6], p[7]);
            }
        }
        __syncthreads();

        // phase 2: acc[q][d] += P[k][q] * v[d][k], each half covers 32 k
#pragma unroll 4
        for (int kk = 0; kk < 32; ++kk) {
            int k = kh * 32 + kk;
            ulonglong2 pa = *(const ulonglong2*)&P_s[k * 128 + tq2 * 8];
            ulonglong2 pb = *(const ulonglong2*)&P_s[k * 128 + tq2 * 8 + 4];
            u64 ap[4] = {pa.x, pa.y, pb.x, pb.y};
            if (td2 == 0) {
#pragma unroll
                for (int jh = 0; jh < 4; ++jh) lacc[jh] = add2(lacc[jh], ap[jh]);
            }
            u64 bp[8];
#pragma unroll
            for (int jd = 0; jd < 8; ++jd) bp[jd] = bcast2(v_s[(td2 * 8 + jd) * 65 + k]);
#pragma unroll
            for (int jh = 0; jh < 4; ++jh)
#pragma unroll
                for (int jd = 0; jd < 8; ++jd) acc[jh][jd] = fma2(ap[jh], bp[jd], acc[jh][jd]);
        }
        __syncthreads();
    }

    // epilogue: merge the two k-halves, apply 1/l, write out.
    if (td2 == 0) {
#pragma unroll
        for (int jh = 0; jh < 4; ++jh)
            ((u64*)l_s)[kh * 64 + tq2 * 4 + jh] = lacc[jh];
    }
    float* mrg = P_s;   // [d][128]
    if (kh == 0) {
#pragma unroll
        for (int jd = 0; jd < 8; ++jd) {
            int d = td2 * 8 + jd;
#pragma unroll
            for (int jh = 0; jh < 4; ++jh)
                *(u64*)&mrg[d * 128 + tq2 * 8 + 2 * jh] = acc[jh][jd];
        }
    }
    __syncthreads();
    if (kh == 1) {
        u64 linv[4];
#pragma unroll
        for (int jh = 0; jh < 4; ++jh) {
            u64 lsum = add2(((u64*)l_s)[tq2 * 4 + jh], ((u64*)l_s)[64 + tq2 * 4 + jh]);
            float2 lv = unpk2(lsum);
            linv[jh] = pack2(1.f / lv.x, 1.f / lv.y);
        }
#pragma unroll
        for (int jd = 0; jd < 8; ++jd) {
            int d = td2 * 8 + jd;
            u64 s[4];
#pragma unroll
            for (int jh = 0; jh < 4; ++jh) {
                u64 m = *(const u64*)&mrg[d * 128 + tq2 * 8 + 2 * jh];
                s[jh] = mul2(add2(m, acc[jh][jd]), linv[jh]);
            }
            float* op = out + ((size_t)b * DEPTH + nh * HD + d) * PQ + q0 + tq2 * 8;
            *(ulonglong2*)(op)     = make_ulonglong2(s[0], s[1]);
            *(ulonglong2*)(op + 4) = make_ulonglong2(s[2], s[3]);
        }
    }
}

// ---------------- launch ----------------
extern "C" void kernel_launch(void* const* d_in, const int* in_sizes, int n_in,
                              void* d_out, int out_size)
{
    (void)in_sizes; (void)n_in; (void)out_size;
    const float* xq    = (const float*)d_in[0];
    const float* xkv   = (const float*)d_in[1];
    const float* wq    = (const float*)d_in[2];
    const float* wk    = (const float*)d_in[3];
    const float* wv    = (const float*)d_in[4];
    const float* emb_q = (const float*)d_in[5];
    const float* emb_k = (const float*)d_in[6];
    float* out = (float*)d_out;

    float *q_p, *k_p, *v_p, *qc_p, *kc_p;
    cudaGetSymbolAddress((void**)&q_p,  g_q);
    cudaGetSymbolAddress((void**)&k_p,  g_k);
    cudaGetSymbolAddress((void**)&v_p,  g_v);
    cudaGetSymbolAddress((void**)&qc_p, g_qc);
    cudaGetSymbolAddress((void**)&kc_p, g_kc);

    const int NQC = B_ * NH * CG * PQ;
    const int NKC = B_ * NH * CG * PK;

    // launch 0: zero both conv outputs
    zero_kernel<<<(NQC + NKC + 1023) / 1024, 1024>>>(qc_p, NQC, kc_p, NKC);

    // launch 1: all three projections (768 blocks)
    proj_all_kernel<<<768, 256>>>(wq, xq, q_p, wk, wv, xkv, k_p, v_p);

    // launch 2: both conv sides (1280 uniform blocks)
    compress_all_kernel<<<1280, 256>>>(q_p, emb_q, qc_p, k_p, emb_k, kc_p);

    // launch 3: attention
    cudaFuncSetAttribute(attn_kernel, cudaFuncAttributeMaxDynamicSharedMemorySize,
                         ATTN_SMEM_FLOATS * sizeof(float));
    attn_kernel<<<dim3(PQ / 128, B_ * NH), 256, ATTN_SMEM_FLOATS * sizeof(float)>>>(out);
}